// round 13
// baseline (speedup 1.0000x reference)
#include <cuda_runtime.h>
#include <cuda_fp16.h>
#include <cstdint>

// -------------------- fp16 scratch (device globals) ------------------------
__device__ __half h_x  [2097152];   // [2,2048,512]
__device__ __half h_x1 [2097152];
__device__ __half h_wqv[524288];    // [512,1024]
__device__ __half h_wk [262144];    // [512,512]
__device__ __half h_wout[262144];   // [512,512]
__device__ __half g_q[2097152];     // [b,h,n,d]
__device__ __half g_k[2097152];     // [b,h,m,d]
__device__ __half g_v[2097152];     // [b,h,m,d]
__device__ __half g_o[2097152];     // [b,n,512]

__device__ __forceinline__ uint32_t smaddr(const void* p) {
    return (uint32_t)__cvta_generic_to_shared(p);
}
#define CP16(dst_u32, src_ptr) \
    asm volatile("cp.async.cg.shared.global [%0], [%1], 16;\n" \
                 :: "r"(dst_u32), "l"(src_ptr))
#define CPCOMMIT() asm volatile("cp.async.commit_group;\n" ::)
#define CPWAIT0()  asm volatile("cp.async.wait_group 0;\n" ::)

__device__ __forceinline__ float ex2f(float x) {
    float r;
    asm("ex2.approx.ftz.f32 %0, %1;" : "=f"(r) : "f"(x));
    return r;
}
__device__ __forceinline__ uint32_t pk(float a, float b) {
    __half2 h = __floats2half2_rn(a, b);
    return *reinterpret_cast<uint32_t*>(&h);
}
__device__ __forceinline__ void mma_h(float c[4],
                                      uint32_t a0, uint32_t a1, uint32_t a2, uint32_t a3,
                                      uint32_t b0, uint32_t b1) {
    asm volatile(
        "mma.sync.aligned.m16n8k16.row.col.f32.f16.f16.f32 "
        "{%0,%1,%2,%3}, {%4,%5,%6,%7}, {%8,%9}, {%0,%1,%2,%3};\n"
        : "+f"(c[0]), "+f"(c[1]), "+f"(c[2]), "+f"(c[3])
        : "r"(a0), "r"(a1), "r"(a2), "r"(a3), "r"(b0), "r"(b1));
}
__device__ __forceinline__ void ldsm4(uint32_t& r0, uint32_t& r1,
                                      uint32_t& r2, uint32_t& r3, uint32_t addr) {
    asm volatile(
        "ldmatrix.sync.aligned.m8n8.x4.shared.b16 {%0,%1,%2,%3}, [%4];\n"
        : "=r"(r0), "=r"(r1), "=r"(r2), "=r"(r3) : "r"(addr));
}
__device__ __forceinline__ void ldsm4t(uint32_t& r0, uint32_t& r1,
                                       uint32_t& r2, uint32_t& r3, uint32_t addr) {
    asm volatile(
        "ldmatrix.sync.aligned.m8n8.x4.trans.shared.b16 {%0,%1,%2,%3}, [%4];\n"
        : "=r"(r0), "=r"(r1), "=r"(r2), "=r"(r3) : "r"(addr));
}

// -------------------- fp32 -> fp16 conversion ------------------------------
__global__ void __launch_bounds__(256)
convert_k(const float* __restrict__ x, const float* __restrict__ x1,
          const float* __restrict__ wqv, const float* __restrict__ wk,
          const float* __restrict__ wout)
{
    const float* src;
    __half* dst;
    int nq;
    switch (blockIdx.y) {
        case 0: src = x;    dst = h_x;    nq = 524288; break;
        case 1: src = x1;   dst = h_x1;   nq = 524288; break;
        case 2: src = wqv;  dst = h_wqv;  nq = 131072; break;
        case 3: src = wk;   dst = h_wk;   nq = 65536;  break;
        default: src = wout; dst = h_wout; nq = 65536; break;
    }
    const int i = blockIdx.x * 256 + threadIdx.x;
    if (i < nq) {
        float4 v = reinterpret_cast<const float4*>(src)[i];
        uint2 o = { pk(v.x, v.y), pk(v.z, v.w) };
        reinterpret_cast<uint2*>(dst)[i] = o;
    }
}

// ---------------------------------------------------------------------------
// fp16 GEMM: CTA tile 64x128, 256 thr (8 warps 4x2, warp tile 16x64),
// K chunks 32, 2-stage cp.async. Halved M-tile vs round 9 -> double grid,
// shorter per-CTA latency, fewer regs.
// MODE 3: fused qv+k projection — blockIdx.x<8: x@W_qv cols; else x1@W_k.
// MODE 2: g_o@h_wout + bias -> out.
// ---------------------------------------------------------------------------
#define HA_LD 20
#define HB_LD 68
#define H_STAGE (64 * HA_LD + 32 * HB_LD)   // 3456 u32

template <int MODE>
__global__ void __launch_bounds__(256, 2)
gemm_h(const float* __restrict__ bias, float* __restrict__ Cout)
{
    extern __shared__ uint32_t sm[];
    const int tid  = threadIdx.x;
    const int lane = tid & 31;
    const int w    = tid >> 5;
    const int g    = lane >> 2;
    const int tg   = lane & 3;
    const int wr   = w >> 1;     // 0..3 (16-row slots)
    const int wc   = w & 1;      // 0..1 (64-col halves)
    const int row0 = blockIdx.y * 64;

    bool isQV = true;
    int col0, ncols;
    const __half* Ap;
    const __half* Wp;
    if (MODE == 3) {
        isQV = (blockIdx.x < 8);
        col0 = isQV ? blockIdx.x * 128 : (blockIdx.x - 8) * 128;
        ncols = isQV ? 1024 : 512;
        Ap = isQV ? h_x : h_x1;
        Wp = isQV ? h_wqv : h_wk;
    } else {
        col0 = blockIdx.x * 128;
        ncols = 512;
        Ap = g_o;
        Wp = h_wout;
    }

    uint32_t* const AsS[2] = { sm, sm + H_STAGE };
    uint32_t* const BsS[2] = { sm + 64 * HA_LD, sm + H_STAGE + 64 * HA_LD };

    float acc[8][4] = {};

    // prologue: chunk 0 (A: 64 rows x 32 cols; B: 32 rows x 128 cols)
    {
        const int r = tid >> 2, q = tid & 3;
        CP16(smaddr(&AsS[0][r * HA_LD + q * 4]),
             Ap + (size_t)(row0 + r) * 512 + q * 8);
    }
#pragma unroll
    for (int i = 0; i < 2; i++) {
        const int idx = tid + i * 256;
        const int r = idx >> 4, q = idx & 15;
        CP16(smaddr(&BsS[0][r * HB_LD + q * 4]),
             Wp + (size_t)r * ncols + col0 + q * 8);
    }
    CPCOMMIT();

    for (int ch = 0; ch < 16; ch++) {
        CPWAIT0();
        __syncthreads();
        if (ch < 15) {
            const int k0 = (ch + 1) * 32;
            const int s  = (ch + 1) & 1;
            {
                const int r = tid >> 2, q = tid & 3;
                CP16(smaddr(&AsS[s][r * HA_LD + q * 4]),
                     Ap + (size_t)(row0 + r) * 512 + k0 + q * 8);
            }
#pragma unroll
            for (int i = 0; i < 2; i++) {
                const int idx = tid + i * 256;
                const int r = idx >> 4, q = idx & 15;
                CP16(smaddr(&BsS[s][r * HB_LD + q * 4]),
                     Wp + (size_t)(k0 + r) * ncols + col0 + q * 8);
            }
            CPCOMMIT();
        }
        const uint32_t* as = AsS[ch & 1];
        const __half* bsh = reinterpret_cast<const __half*>(BsS[ch & 1]);

#pragma unroll
        for (int kt = 0; kt < 2; kt++) {
            const int r = wr * 16;
            const uint32_t a0 = as[(r + g) * HA_LD + kt * 8 + tg];
            const uint32_t a1 = as[(r + g + 8) * HA_LD + kt * 8 + tg];
            const uint32_t a2 = as[(r + g) * HA_LD + kt * 8 + tg + 4];
            const uint32_t a3 = as[(r + g + 8) * HA_LD + kt * 8 + tg + 4];
            uint32_t bfr[8][2];
#pragma unroll
            for (int ntp = 0; ntp < 4; ntp++) {
                const int kr   = kt * 16 + ((lane >> 3) & 1) * 8 + (lane & 7);
                const int ncol = wc * 64 + (ntp * 2 + (lane >> 4)) * 8;
                ldsm4t(bfr[ntp * 2][0], bfr[ntp * 2][1],
                       bfr[ntp * 2 + 1][0], bfr[ntp * 2 + 1][1],
                       smaddr(&bsh[kr * (HB_LD * 2) + ncol]));
            }
#pragma unroll
            for (int nt = 0; nt < 8; nt++)
                mma_h(acc[nt], a0, a1, a2, a3, bfr[nt][0], bfr[nt][1]);
        }
    }

#pragma unroll
    for (int nt = 0; nt < 8; nt++) {
#pragma unroll
        for (int half = 0; half < 2; half++) {
            const int row = row0 + wr * 16 + g + half * 8;
            const int col = col0 + wc * 64 + nt * 8 + 2 * tg;
            const float v0 = acc[nt][half * 2 + 0];
            const float v1 = acc[nt][half * 2 + 1];
            const int b = row >> 11, n = row & 2047;
            if (MODE == 3) {
                __half* dst;
                if (isQV) {
                    if (col < 512) {
                        const int h = col >> 6, d = col & 63;
                        dst = &g_q[((size_t)(b * 8 + h) * 2048 + n) * 64 + d];
                    } else {
                        const int c2 = col - 512;
                        const int h = c2 >> 6, d = c2 & 63;
                        dst = &g_v[((size_t)(b * 8 + h) * 2048 + n) * 64 + d];
                    }
                } else {
                    const int h = col >> 6, d = col & 63;
                    dst = &g_k[((size_t)(b * 8 + h) * 2048 + n) * 64 + d];
                }
                *reinterpret_cast<uint32_t*>(dst) = pk(v0, v1);
            } else {
                float* dst = &Cout[(size_t)row * 512 + col];
                *reinterpret_cast<float2*>(dst) =
                    make_float2(v0 + bias[col], v1 + bias[col + 1]);
            }
        }
    }
}

// ---------------------------------------------------------------------------
// Fused attention (proven 160.5us config, UNCHANGED): fp16 HMMA, 2-stage
// cp.async K/V/amat, P in registers, exp/PV interleaved.
// smem u32: Qs[128][36] | Ks[2][32][36] | Vs[2][32][36] | Am[2][128][36]
// ---------------------------------------------------------------------------
#define AQ_LD 36
#define ATT_SMEM_W (128 * AQ_LD + 4 * 32 * AQ_LD + 2 * 128 * AQ_LD)

__global__ void __launch_bounds__(256, 2)
attn_h(const float* __restrict__ amat,
       const float* __restrict__ dots_para,
       const float* __restrict__ mat_para)
{
    extern __shared__ uint32_t sm[];
    uint32_t* const Qs = sm;
    uint32_t* const KsS[2] = { sm + 128 * AQ_LD, sm + 160 * AQ_LD };
    uint32_t* const VsS[2] = { sm + 192 * AQ_LD, sm + 224 * AQ_LD };
    uint32_t* const AmS[2] = { sm + 256 * AQ_LD, sm + 384 * AQ_LD };

    const int tid  = threadIdx.x;
    const int lane = tid & 31;
    const int w    = tid >> 5;
    const int g    = lane >> 2;
    const int tg   = lane & 3;
    const int b  = blockIdx.z, h = blockIdx.y;
    const int n0 = blockIdx.x * 128;

    const float qscale = 0.125f * dots_para[0] * 1.44269504f;
    const float mp = mat_para[0] * 1.44269504f;

    const size_t qbase  = ((size_t)(b * 8 + h) * 2048 + n0) * 64;
    const size_t kvbase = (size_t)(b * 8 + h) * 2048 * 64;
    const size_t abase  = ((size_t)(b * 8 + h) * 2048 + n0) * 2048;

#pragma unroll
    for (int i = 0; i < 4; i++) {
        const int idx = tid + i * 256;
        const int r = idx >> 3, q = idx & 7;
        CP16(smaddr(&Qs[r * AQ_LD + q * 4]), g_q + qbase + (size_t)r * 64 + q * 8);
    }
    {
        const int r = tid >> 3, q = tid & 7;
        CP16(smaddr(&KsS[0][r * AQ_LD + q * 4]), g_k + kvbase + (size_t)r * 64 + q * 8);
        CP16(smaddr(&VsS[0][r * AQ_LD + q * 4]), g_v + kvbase + (size_t)r * 64 + q * 8);
    }
#pragma unroll
    for (int i = 0; i < 4; i++) {
        const int idx = tid + i * 256;
        const int r = idx >> 3, c = (idx & 7) * 4;
        CP16(smaddr(&AmS[0][r * AQ_LD + c]), amat + abase + (size_t)r * 2048 + c);
    }
    CPCOMMIT();

    float O[8][4] = {};
    float rl0 = 0.f, rl1 = 0.f;
    const int rowA = w * 16 + g;

    for (int ch = 0; ch < 64; ch++) {
        CPWAIT0();
        __syncthreads();
        if (ch < 63) {
            const size_t m1 = (size_t)(ch + 1) * 32;
            const int s = (ch + 1) & 1;
            {
                const int r = tid >> 3, q = tid & 7;
                CP16(smaddr(&KsS[s][r * AQ_LD + q * 4]),
                     g_k + kvbase + (m1 + r) * 64 + q * 8);
                CP16(smaddr(&VsS[s][r * AQ_LD + q * 4]),
                     g_v + kvbase + (m1 + r) * 64 + q * 8);
            }
#pragma unroll
            for (int i = 0; i < 4; i++) {
                const int idx = tid + i * 256;
                const int r = idx >> 3, c = (idx & 7) * 4;
                CP16(smaddr(&AmS[s][r * AQ_LD + c]),
                     amat + abase + (size_t)r * 2048 + m1 + c);
            }
            CPCOMMIT();
        }
        const __half* Qsh = reinterpret_cast<const __half*>(Qs);
        const __half* Ksh = reinterpret_cast<const __half*>(KsS[ch & 1]);
        const __half* Vsh = reinterpret_cast<const __half*>(VsS[ch & 1]);
        const float*  Am  = reinterpret_cast<const float*>(AmS[ch & 1]);

        float S[4][4] = {};
#pragma unroll
        for (int kt = 0; kt < 4; kt++) {
            uint32_t aq0, aq1, aq2, aq3;
            {
                const int mr = w * 16 + (lane & 15);
                const int kc = kt * 16 + (lane >> 4) * 8;
                ldsm4(aq0, aq1, aq2, aq3, smaddr(&Qsh[mr * (AQ_LD * 2) + kc]));
            }
#pragma unroll
            for (int ntp = 0; ntp < 2; ntp++) {
                uint32_t kb0, kb1, kb2, kb3;
                const int nr = ntp * 16 + ((lane >> 4) & 1) * 8 + (lane & 7);
                const int kc = kt * 16 + ((lane >> 3) & 1) * 8;
                ldsm4(kb0, kb1, kb2, kb3, smaddr(&Ksh[nr * (AQ_LD * 2) + kc]));
                mma_h(S[ntp * 2],     aq0, aq1, aq2, aq3, kb0, kb1);
                mma_h(S[ntp * 2 + 1], aq0, aq1, aq2, aq3, kb2, kb3);
            }
        }

#pragma unroll
        for (int j = 0; j < 2; j++) {
            uint32_t pva[4];
#pragma unroll
            for (int t = 0; t < 2; t++) {
                const int nt = j * 2 + t;
                const int acol = nt * 8 + 2 * tg;
                const float2 amA = *reinterpret_cast<const float2*>(
                    &Am[rowA * AQ_LD + acol]);
                const float2 amB = *reinterpret_cast<const float2*>(
                    &Am[(rowA + 8) * AQ_LD + acol]);
                const float p0 = ex2f(S[nt][0] * qscale + amA.x * mp);
                const float p1 = ex2f(S[nt][1] * qscale + amA.y * mp);
                const float p2 = ex2f(S[nt][2] * qscale + amB.x * mp);
                const float p3 = ex2f(S[nt][3] * qscale + amB.y * mp);
                rl0 += p0 + p1;
                rl1 += p2 + p3;
                pva[t * 2 + 0] = pk(p0, p1);
                pva[t * 2 + 1] = pk(p2, p3);
            }
            uint32_t vb[8][2];
#pragma unroll
            for (int ntp = 0; ntp < 4; ntp++) {
                const int mr = j * 16 + ((lane >> 3) & 1) * 8 + (lane & 7);
                const int dc = (ntp * 2 + (lane >> 4)) * 8;
                ldsm4t(vb[ntp * 2][0], vb[ntp * 2][1],
                       vb[ntp * 2 + 1][0], vb[ntp * 2 + 1][1],
                       smaddr(&Vsh[mr * (AQ_LD * 2) + dc]));
            }
#pragma unroll
            for (int nt = 0; nt < 8; nt++)
                mma_h(O[nt], pva[0], pva[1], pva[2], pva[3],
                      vb[nt][0], vb[nt][1]);
        }
    }

#pragma unroll
    for (int off = 1; off <= 2; off <<= 1) {
        rl0 += __shfl_xor_sync(0xffffffffu, rl0, off);
        rl1 += __shfl_xor_sync(0xffffffffu, rl1, off);
    }
    const float inv0 = 1.0f / rl0;
    const float inv1 = 1.0f / rl1;
    const int grow = n0 + rowA;
#pragma unroll
    for (int nt = 0; nt < 8; nt++) {
        const int col = h * 64 + nt * 8 + 2 * tg;
        *reinterpret_cast<uint32_t*>(&g_o[((size_t)b * 2048 + grow) * 512 + col]) =
            pk(O[nt][0] * inv0, O[nt][1] * inv0);
        *reinterpret_cast<uint32_t*>(&g_o[((size_t)b * 2048 + grow + 8) * 512 + col]) =
            pk(O[nt][2] * inv1, O[nt][3] * inv1);
    }
}

// ---------------------------------------------------------------------------
extern "C" void kernel_launch(void* const* d_in, const int* in_sizes, int n_in,
                              void* d_out, int out_size)
{
    const float* x    = (const float*)d_in[0];
    const float* x1   = (const float*)d_in[1];
    const float* amat = (const float*)d_in[2];
    const float* dp   = (const float*)d_in[3];
    const float* mp   = (const float*)d_in[4];
    const float* Wqv  = (const float*)d_in[5];
    const float* Wk   = (const float*)d_in[6];
    const float* Wout = (const float*)d_in[7];
    const float* bout = (const float*)d_in[8];
    float* out = (float*)d_out;

    const int gsmem = 2 * H_STAGE * (int)sizeof(uint32_t);   // 27,648 B
    const int asmem = ATT_SMEM_W * (int)sizeof(uint32_t);    // 73,728 B
    cudaFuncSetAttribute((const void*)attn_h,
                         cudaFuncAttributeMaxDynamicSharedMemorySize, asmem);

    // fp32 -> fp16 staging
    convert_k<<<dim3(2048, 5), 256>>>(x, x1, Wqv, Wk, Wout);
    // fused q,v,k projection: 64-row tiles -> 768 CTAs
    gemm_h<3><<<dim3(12, 64), 256, gsmem>>>(nullptr, nullptr);
    // fused attention
    attn_h<<<dim3(16, 8, 2), 256, asmem>>>(amat, dp, mp);
    // output projection + bias: 64-row tiles -> 256 CTAs
    gemm_h<2><<<dim3(4, 64), 256, gsmem>>>(bout, out);
}

// round 14
// speedup vs baseline: 1.1279x; 1.1279x over previous
#include <cuda_runtime.h>
#include <cuda_fp16.h>
#include <cstdint>

// -------------------- fp16 scratch (device globals) ------------------------
__device__ __half h_x  [2097152];   // [2,2048,512]
__device__ __half h_x1 [2097152];
__device__ __half h_wqv[524288];    // [512,1024]
__device__ __half h_wk [262144];    // [512,512]
__device__ __half h_wout[262144];   // [512,512]
__device__ __half g_q[2097152];     // [b,h,n,d]
__device__ __half g_k[2097152];     // [b,h,m,d]
__device__ __half g_v[2097152];     // [b,h,m,d]
__device__ __half g_o[2097152];     // [b,n,512]

__device__ __forceinline__ uint32_t smaddr(const void* p) {
    return (uint32_t)__cvta_generic_to_shared(p);
}
#define CP16(dst_u32, src_ptr) \
    asm volatile("cp.async.cg.shared.global [%0], [%1], 16;\n" \
                 :: "r"(dst_u32), "l"(src_ptr))
#define CPCOMMIT() asm volatile("cp.async.commit_group;\n" ::)
#define CPWAIT0()  asm volatile("cp.async.wait_group 0;\n" ::)

__device__ __forceinline__ float ex2f(float x) {
    float r;
    asm("ex2.approx.ftz.f32 %0, %1;" : "=f"(r) : "f"(x));
    return r;
}
__device__ __forceinline__ uint32_t pk(float a, float b) {
    __half2 h = __floats2half2_rn(a, b);
    return *reinterpret_cast<uint32_t*>(&h);
}
__device__ __forceinline__ void mma_h(float c[4],
                                      uint32_t a0, uint32_t a1, uint32_t a2, uint32_t a3,
                                      uint32_t b0, uint32_t b1) {
    asm volatile(
        "mma.sync.aligned.m16n8k16.row.col.f32.f16.f16.f32 "
        "{%0,%1,%2,%3}, {%4,%5,%6,%7}, {%8,%9}, {%0,%1,%2,%3};\n"
        : "+f"(c[0]), "+f"(c[1]), "+f"(c[2]), "+f"(c[3])
        : "r"(a0), "r"(a1), "r"(a2), "r"(a3), "r"(b0), "r"(b1));
}
__device__ __forceinline__ void ldsm4(uint32_t& r0, uint32_t& r1,
                                      uint32_t& r2, uint32_t& r3, uint32_t addr) {
    asm volatile(
        "ldmatrix.sync.aligned.m8n8.x4.shared.b16 {%0,%1,%2,%3}, [%4];\n"
        : "=r"(r0), "=r"(r1), "=r"(r2), "=r"(r3) : "r"(addr));
}
__device__ __forceinline__ void ldsm4t(uint32_t& r0, uint32_t& r1,
                                       uint32_t& r2, uint32_t& r3, uint32_t addr) {
    asm volatile(
        "ldmatrix.sync.aligned.m8n8.x4.trans.shared.b16 {%0,%1,%2,%3}, [%4];\n"
        : "=r"(r0), "=r"(r1), "=r"(r2), "=r"(r3) : "r"(addr));
}

// -------------------- fp32 -> fp16 conversion ------------------------------
__global__ void __launch_bounds__(256)
convert_k(const float* __restrict__ x, const float* __restrict__ x1,
          const float* __restrict__ wqv, const float* __restrict__ wk,
          const float* __restrict__ wout)
{
    const float* src;
    __half* dst;
    int nq;
    switch (blockIdx.y) {
        case 0: src = x;    dst = h_x;    nq = 524288; break;
        case 1: src = x1;   dst = h_x1;   nq = 524288; break;
        case 2: src = wqv;  dst = h_wqv;  nq = 131072; break;
        case 3: src = wk;   dst = h_wk;   nq = 65536;  break;
        default: src = wout; dst = h_wout; nq = 65536; break;
    }
    const int i = blockIdx.x * 256 + threadIdx.x;
    if (i < nq) {
        float4 v = reinterpret_cast<const float4*>(src)[i];
        uint2 o = { pk(v.x, v.y), pk(v.z, v.w) };
        reinterpret_cast<uint2*>(dst)[i] = o;
    }
}

// ---------------------------------------------------------------------------
// fp16 GEMM: CTA tile (64*MT)x128, 256 thr (8 warps 4x2, warp (16*MT)x64),
// K chunks 32, 2-stage cp.async.
// MODE 3 (MT=2, 128-row tiles): fused qv+k projection.
// MODE 2 (MT=1, 64-row tiles): g_o@h_wout + bias -> out.
// ---------------------------------------------------------------------------
#define HA_LD 20
#define HB_LD 68

template <int MODE, int MT>
__global__ void __launch_bounds__(256, 2)
gemm_h(const float* __restrict__ bias, float* __restrict__ Cout)
{
    constexpr int STAGE = 64 * MT * HA_LD + 32 * HB_LD;
    extern __shared__ uint32_t sm[];
    const int tid  = threadIdx.x;
    const int lane = tid & 31;
    const int w    = tid >> 5;
    const int g    = lane >> 2;
    const int tg   = lane & 3;
    const int wr   = w >> 1;
    const int wc   = w & 1;
    const int row0 = blockIdx.y * (64 * MT);

    bool isQV = true;
    int col0, ncols;
    const __half* Ap;
    const __half* Wp;
    if (MODE == 3) {
        isQV = (blockIdx.x < 8);
        col0 = isQV ? blockIdx.x * 128 : (blockIdx.x - 8) * 128;
        ncols = isQV ? 1024 : 512;
        Ap = isQV ? h_x : h_x1;
        Wp = isQV ? h_wqv : h_wk;
    } else {
        col0 = blockIdx.x * 128;
        ncols = 512;
        Ap = g_o;
        Wp = h_wout;
    }

    uint32_t* const AsS[2] = { sm, sm + STAGE };
    uint32_t* const BsS[2] = { sm + 64 * MT * HA_LD, sm + STAGE + 64 * MT * HA_LD };

    float acc[MT][8][4] = {};

    // prologue: chunk 0
#pragma unroll
    for (int i = 0; i < MT; i++) {
        const int idx = tid + i * 256;
        const int r = idx >> 2, q = idx & 3;
        CP16(smaddr(&AsS[0][r * HA_LD + q * 4]),
             Ap + (size_t)(row0 + r) * 512 + q * 8);
    }
#pragma unroll
    for (int i = 0; i < 2; i++) {
        const int idx = tid + i * 256;
        const int r = idx >> 4, q = idx & 15;
        CP16(smaddr(&BsS[0][r * HB_LD + q * 4]),
             Wp + (size_t)r * ncols + col0 + q * 8);
    }
    CPCOMMIT();

    for (int ch = 0; ch < 16; ch++) {
        CPWAIT0();
        __syncthreads();
        if (ch < 15) {
            const int k0 = (ch + 1) * 32;
            const int s  = (ch + 1) & 1;
#pragma unroll
            for (int i = 0; i < MT; i++) {
                const int idx = tid + i * 256;
                const int r = idx >> 2, q = idx & 3;
                CP16(smaddr(&AsS[s][r * HA_LD + q * 4]),
                     Ap + (size_t)(row0 + r) * 512 + k0 + q * 8);
            }
#pragma unroll
            for (int i = 0; i < 2; i++) {
                const int idx = tid + i * 256;
                const int r = idx >> 4, q = idx & 15;
                CP16(smaddr(&BsS[s][r * HB_LD + q * 4]),
                     Wp + (size_t)(k0 + r) * ncols + col0 + q * 8);
            }
            CPCOMMIT();
        }
        const uint32_t* as = AsS[ch & 1];
        const __half* bsh = reinterpret_cast<const __half*>(BsS[ch & 1]);

#pragma unroll
        for (int kt = 0; kt < 2; kt++) {
            uint32_t a[MT][4];
#pragma unroll
            for (int mt = 0; mt < MT; mt++) {
                const int r = wr * 16 * MT + mt * 16;
                a[mt][0] = as[(r + g) * HA_LD + kt * 8 + tg];
                a[mt][1] = as[(r + g + 8) * HA_LD + kt * 8 + tg];
                a[mt][2] = as[(r + g) * HA_LD + kt * 8 + tg + 4];
                a[mt][3] = as[(r + g + 8) * HA_LD + kt * 8 + tg + 4];
            }
            uint32_t bfr[8][2];
#pragma unroll
            for (int ntp = 0; ntp < 4; ntp++) {
                const int kr   = kt * 16 + ((lane >> 3) & 1) * 8 + (lane & 7);
                const int ncol = wc * 64 + (ntp * 2 + (lane >> 4)) * 8;
                ldsm4t(bfr[ntp * 2][0], bfr[ntp * 2][1],
                       bfr[ntp * 2 + 1][0], bfr[ntp * 2 + 1][1],
                       smaddr(&bsh[kr * (HB_LD * 2) + ncol]));
            }
#pragma unroll
            for (int nt = 0; nt < 8; nt++)
#pragma unroll
                for (int mt = 0; mt < MT; mt++)
                    mma_h(acc[mt][nt], a[mt][0], a[mt][1], a[mt][2], a[mt][3],
                          bfr[nt][0], bfr[nt][1]);
        }
    }

#pragma unroll
    for (int mt = 0; mt < MT; mt++) {
#pragma unroll
        for (int nt = 0; nt < 8; nt++) {
#pragma unroll
            for (int half = 0; half < 2; half++) {
                const int row = row0 + wr * 16 * MT + mt * 16 + g + half * 8;
                const int col = col0 + wc * 64 + nt * 8 + 2 * tg;
                const float v0 = acc[mt][nt][half * 2 + 0];
                const float v1 = acc[mt][nt][half * 2 + 1];
                const int b = row >> 11, n = row & 2047;
                if (MODE == 3) {
                    __half* dst;
                    if (isQV) {
                        if (col < 512) {
                            const int h = col >> 6, d = col & 63;
                            dst = &g_q[((size_t)(b * 8 + h) * 2048 + n) * 64 + d];
                        } else {
                            const int c2 = col - 512;
                            const int h = c2 >> 6, d = c2 & 63;
                            dst = &g_v[((size_t)(b * 8 + h) * 2048 + n) * 64 + d];
                        }
                    } else {
                        const int h = col >> 6, d = col & 63;
                        dst = &g_k[((size_t)(b * 8 + h) * 2048 + n) * 64 + d];
                    }
                    *reinterpret_cast<uint32_t*>(dst) = pk(v0, v1);
                } else {
                    float* dst = &Cout[(size_t)row * 512 + col];
                    *reinterpret_cast<float2*>(dst) =
                        make_float2(v0 + bias[col], v1 + bias[col + 1]);
                }
            }
        }
    }
}

// ---------------------------------------------------------------------------
// Fused attention v2: 128 threads, 4 warps x 32 q-rows. Q fragments hoisted
// into registers (chunk-invariant). K/V fragments loaded half as many times
// as the 8-warp version (B-frags are warp-independent). Same smem layout,
// same math order -> identical numerics to the 160.5us kernel.
// smem u32: Qs[128][36] | Ks[2][32][36] | Vs[2][32][36] | Am[2][128][36]
// ---------------------------------------------------------------------------
#define AQ_LD 36
#define ATT_SMEM_W (128 * AQ_LD + 4 * 32 * AQ_LD + 2 * 128 * AQ_LD)

__global__ void __launch_bounds__(128, 3)
attn_h(const float* __restrict__ amat,
       const float* __restrict__ dots_para,
       const float* __restrict__ mat_para)
{
    extern __shared__ uint32_t sm[];
    uint32_t* const Qs = sm;
    uint32_t* const KsS[2] = { sm + 128 * AQ_LD, sm + 160 * AQ_LD };
    uint32_t* const VsS[2] = { sm + 192 * AQ_LD, sm + 224 * AQ_LD };
    uint32_t* const AmS[2] = { sm + 256 * AQ_LD, sm + 384 * AQ_LD };

    const int tid  = threadIdx.x;
    const int lane = tid & 31;
    const int w    = tid >> 5;            // 0..3, owns q-rows [w*32, w*32+32)
    const int g    = lane >> 2;
    const int tg   = lane & 3;
    const int b  = blockIdx.z, h = blockIdx.y;
    const int n0 = blockIdx.x * 128;

    const float qscale = 0.125f * dots_para[0] * 1.44269504f;
    const float mp = mat_para[0] * 1.44269504f;

    const size_t qbase  = ((size_t)(b * 8 + h) * 2048 + n0) * 64;
    const size_t kvbase = (size_t)(b * 8 + h) * 2048 * 64;
    const size_t abase  = ((size_t)(b * 8 + h) * 2048 + n0) * 2048;

    // Q (128x64 fp16) + K/V chunk 0 + amat chunk 0 (128-thread loops)
#pragma unroll
    for (int i = 0; i < 8; i++) {
        const int idx = tid + i * 128;
        const int r = idx >> 3, q = idx & 7;
        CP16(smaddr(&Qs[r * AQ_LD + q * 4]), g_q + qbase + (size_t)r * 64 + q * 8);
    }
#pragma unroll
    for (int i = 0; i < 2; i++) {
        const int idx = tid + i * 128;
        const int r = idx >> 3, q = idx & 7;
        CP16(smaddr(&KsS[0][r * AQ_LD + q * 4]), g_k + kvbase + (size_t)r * 64 + q * 8);
        CP16(smaddr(&VsS[0][r * AQ_LD + q * 4]), g_v + kvbase + (size_t)r * 64 + q * 8);
    }
#pragma unroll
    for (int i = 0; i < 8; i++) {
        const int idx = tid + i * 128;
        const int r = idx >> 3, c = (idx & 7) * 4;
        CP16(smaddr(&AmS[0][r * AQ_LD + c]), amat + abase + (size_t)r * 2048 + c);
    }
    CPCOMMIT();

    uint32_t qf[4][2][4];                 // [kt][mt][reg] hoisted Q fragments
    float O[2][8][4] = {};                // [mt][nt][reg]
    float rl[2][2] = {};                  // [mt][row-half]

    for (int ch = 0; ch < 64; ch++) {
        CPWAIT0();
        __syncthreads();
        if (ch == 0) {
            const __half* Qsh = reinterpret_cast<const __half*>(Qs);
#pragma unroll
            for (int kt = 0; kt < 4; kt++) {
#pragma unroll
                for (int mt = 0; mt < 2; mt++) {
                    const int mr = w * 32 + mt * 16 + (lane & 15);
                    const int kc = kt * 16 + (lane >> 4) * 8;
                    ldsm4(qf[kt][mt][0], qf[kt][mt][1], qf[kt][mt][2], qf[kt][mt][3],
                          smaddr(&Qsh[mr * (AQ_LD * 2) + kc]));
                }
            }
        }
        if (ch < 63) {
            const size_t m1 = (size_t)(ch + 1) * 32;
            const int s = (ch + 1) & 1;
#pragma unroll
            for (int i = 0; i < 2; i++) {
                const int idx = tid + i * 128;
                const int r = idx >> 3, q = idx & 7;
                CP16(smaddr(&KsS[s][r * AQ_LD + q * 4]),
                     g_k + kvbase + (m1 + r) * 64 + q * 8);
                CP16(smaddr(&VsS[s][r * AQ_LD + q * 4]),
                     g_v + kvbase + (m1 + r) * 64 + q * 8);
            }
#pragma unroll
            for (int i = 0; i < 8; i++) {
                const int idx = tid + i * 128;
                const int r = idx >> 3, c = (idx & 7) * 4;
                CP16(smaddr(&AmS[s][r * AQ_LD + c]),
                     amat + abase + (size_t)r * 2048 + m1 + c);
            }
            CPCOMMIT();
        }
        const __half* Ksh = reinterpret_cast<const __half*>(KsS[ch & 1]);
        const __half* Vsh = reinterpret_cast<const __half*>(VsS[ch & 1]);
        const float*  Am  = reinterpret_cast<const float*>(AmS[ch & 1]);

        // S = Q @ K^T  (32 q-rows x 32 m-cols per warp)
        float S[2][4][4] = {};
#pragma unroll
        for (int kt = 0; kt < 4; kt++) {
#pragma unroll
            for (int ntp = 0; ntp < 2; ntp++) {
                uint32_t kb0, kb1, kb2, kb3;
                const int nr = ntp * 16 + ((lane >> 4) & 1) * 8 + (lane & 7);
                const int kc = kt * 16 + ((lane >> 3) & 1) * 8;
                ldsm4(kb0, kb1, kb2, kb3, smaddr(&Ksh[nr * (AQ_LD * 2) + kc]));
#pragma unroll
                for (int mt = 0; mt < 2; mt++) {
                    mma_h(S[mt][ntp * 2],     qf[kt][mt][0], qf[kt][mt][1],
                          qf[kt][mt][2], qf[kt][mt][3], kb0, kb1);
                    mma_h(S[mt][ntp * 2 + 1], qf[kt][mt][0], qf[kt][mt][1],
                          qf[kt][mt][2], qf[kt][mt][3], kb2, kb3);
                }
            }
        }

        // exp + PV per 16-row m-half
#pragma unroll
        for (int j = 0; j < 2; j++) {
            uint32_t pva[2][4];
#pragma unroll
            for (int mt = 0; mt < 2; mt++) {
#pragma unroll
                for (int t = 0; t < 2; t++) {
                    const int nt = j * 2 + t;
                    const int rowA = w * 32 + mt * 16 + g;
                    const int acol = nt * 8 + 2 * tg;
                    const float2 amA = *reinterpret_cast<const float2*>(
                        &Am[rowA * AQ_LD + acol]);
                    const float2 amB = *reinterpret_cast<const float2*>(
                        &Am[(rowA + 8) * AQ_LD + acol]);
                    const float p0 = ex2f(S[mt][nt][0] * qscale + amA.x * mp);
                    const float p1 = ex2f(S[mt][nt][1] * qscale + amA.y * mp);
                    const float p2 = ex2f(S[mt][nt][2] * qscale + amB.x * mp);
                    const float p3 = ex2f(S[mt][nt][3] * qscale + amB.y * mp);
                    rl[mt][0] += p0 + p1;
                    rl[mt][1] += p2 + p3;
                    pva[mt][t * 2 + 0] = pk(p0, p1);
                    pva[mt][t * 2 + 1] = pk(p2, p3);
                }
            }
            uint32_t vb[8][2];
#pragma unroll
            for (int ntp = 0; ntp < 4; ntp++) {
                const int mr = j * 16 + ((lane >> 3) & 1) * 8 + (lane & 7);
                const int dc = (ntp * 2 + (lane >> 4)) * 8;
                ldsm4t(vb[ntp * 2][0], vb[ntp * 2][1],
                       vb[ntp * 2 + 1][0], vb[ntp * 2 + 1][1],
                       smaddr(&Vsh[mr * (AQ_LD * 2) + dc]));
            }
#pragma unroll
            for (int nt = 0; nt < 8; nt++)
#pragma unroll
                for (int mt = 0; mt < 2; mt++)
                    mma_h(O[mt][nt], pva[mt][0], pva[mt][1], pva[mt][2], pva[mt][3],
                          vb[nt][0], vb[nt][1]);
        }
    }

    // quad-reduce row sums, normalize, store fp16 (per mt half)
#pragma unroll
    for (int mt = 0; mt < 2; mt++) {
        float r0 = rl[mt][0], r1 = rl[mt][1];
#pragma unroll
        for (int off = 1; off <= 2; off <<= 1) {
            r0 += __shfl_xor_sync(0xffffffffu, r0, off);
            r1 += __shfl_xor_sync(0xffffffffu, r1, off);
        }
        const float inv0 = 1.0f / r0;
        const float inv1 = 1.0f / r1;
        const int grow = n0 + w * 32 + mt * 16 + g;
#pragma unroll
        for (int nt = 0; nt < 8; nt++) {
            const int col = h * 64 + nt * 8 + 2 * tg;
            *reinterpret_cast<uint32_t*>(&g_o[((size_t)b * 2048 + grow) * 512 + col]) =
                pk(O[mt][nt][0] * inv0, O[mt][nt][1] * inv0);
            *reinterpret_cast<uint32_t*>(&g_o[((size_t)b * 2048 + grow + 8) * 512 + col]) =
                pk(O[mt][nt][2] * inv1, O[mt][nt][3] * inv1);
        }
    }
}

// ---------------------------------------------------------------------------
extern "C" void kernel_launch(void* const* d_in, const int* in_sizes, int n_in,
                              void* d_out, int out_size)
{
    const float* x    = (const float*)d_in[0];
    const float* x1   = (const float*)d_in[1];
    const float* amat = (const float*)d_in[2];
    const float* dp   = (const float*)d_in[3];
    const float* mp   = (const float*)d_in[4];
    const float* Wqv  = (const float*)d_in[5];
    const float* Wk   = (const float*)d_in[6];
    const float* Wout = (const float*)d_in[7];
    const float* bout = (const float*)d_in[8];
    float* out = (float*)d_out;

    const int gsmem2 = 2 * (128 * HA_LD + 32 * HB_LD) * (int)sizeof(uint32_t); // 37,888
    const int gsmem1 = 2 * (64 * HA_LD + 32 * HB_LD) * (int)sizeof(uint32_t);  // 27,648
    const int asmem  = ATT_SMEM_W * (int)sizeof(uint32_t);                     // 73,728
    cudaFuncSetAttribute((const void*)attn_h,
                         cudaFuncAttributeMaxDynamicSharedMemorySize, asmem);

    // fp32 -> fp16 staging
    convert_k<<<dim3(2048, 5), 256>>>(x, x1, Wqv, Wk, Wout);
    // fused q,v,k projection: 128x128 tiles -> 384 CTAs (proven best)
    gemm_h<3, 2><<<dim3(12, 32), 256, gsmem2>>>(nullptr, nullptr);
    // fused attention: 4 fat warps, hoisted Q frags
    attn_h<<<dim3(16, 8, 2), 128, asmem>>>(amat, dp, mp);
    // output projection + bias: 64x128 tiles -> 256 CTAs (measured 16.8us)
    gemm_h<2, 1><<<dim3(4, 64), 256, gsmem1>>>(bout, out);
}

// round 15
// speedup vs baseline: 1.1687x; 1.0362x over previous
#include <cuda_runtime.h>
#include <cuda_fp16.h>
#include <cstdint>

// -------------------- fp16 scratch (device globals) ------------------------
__device__ __half h_x  [2097152];   // [2,2048,512]
__device__ __half h_x1 [2097152];
__device__ __half h_wqv[524288];    // [512,1024]
__device__ __half h_wk [262144];    // [512,512]
__device__ __half h_wout[262144];   // [512,512]
__device__ __half g_q[2097152];     // [b,h,n,d]
__device__ __half g_k[2097152];     // [b,h,m,d]
__device__ __half g_v[2097152];     // [b,h,m,d]
__device__ __half g_o[2097152];     // [b,n,512]

__device__ __forceinline__ uint32_t smaddr(const void* p) {
    return (uint32_t)__cvta_generic_to_shared(p);
}
#define CP16(dst_u32, src_ptr) \
    asm volatile("cp.async.cg.shared.global [%0], [%1], 16;\n" \
                 :: "r"(dst_u32), "l"(src_ptr))
#define CPCOMMIT() asm volatile("cp.async.commit_group;\n" ::)
#define CPWAIT0()  asm volatile("cp.async.wait_group 0;\n" ::)

__device__ __forceinline__ float ex2f(float x) {
    float r;
    asm("ex2.approx.ftz.f32 %0, %1;" : "=f"(r) : "f"(x));
    return r;
}
__device__ __forceinline__ uint32_t pk(float a, float b) {
    __half2 h = __floats2half2_rn(a, b);
    return *reinterpret_cast<uint32_t*>(&h);
}
__device__ __forceinline__ void mma_h(float c[4],
                                      uint32_t a0, uint32_t a1, uint32_t a2, uint32_t a3,
                                      uint32_t b0, uint32_t b1) {
    asm volatile(
        "mma.sync.aligned.m16n8k16.row.col.f32.f16.f16.f32 "
        "{%0,%1,%2,%3}, {%4,%5,%6,%7}, {%8,%9}, {%0,%1,%2,%3};\n"
        : "+f"(c[0]), "+f"(c[1]), "+f"(c[2]), "+f"(c[3])
        : "r"(a0), "r"(a1), "r"(a2), "r"(a3), "r"(b0), "r"(b1));
}
__device__ __forceinline__ void ldsm4(uint32_t& r0, uint32_t& r1,
                                      uint32_t& r2, uint32_t& r3, uint32_t addr) {
    asm volatile(
        "ldmatrix.sync.aligned.m8n8.x4.shared.b16 {%0,%1,%2,%3}, [%4];\n"
        : "=r"(r0), "=r"(r1), "=r"(r2), "=r"(r3) : "r"(addr));
}
__device__ __forceinline__ void ldsm4t(uint32_t& r0, uint32_t& r1,
                                       uint32_t& r2, uint32_t& r3, uint32_t addr) {
    asm volatile(
        "ldmatrix.sync.aligned.m8n8.x4.trans.shared.b16 {%0,%1,%2,%3}, [%4];\n"
        : "=r"(r0), "=r"(r1), "=r"(r2), "=r"(r3) : "r"(addr));
}

// -------------------- fp32 -> fp16 conversion ------------------------------
__global__ void __launch_bounds__(256)
convert_k(const float* __restrict__ x, const float* __restrict__ x1,
          const float* __restrict__ wqv, const float* __restrict__ wk,
          const float* __restrict__ wout)
{
    const float* src;
    __half* dst;
    int nq;
    switch (blockIdx.y) {
        case 0: src = x;    dst = h_x;    nq = 524288; break;
        case 1: src = x1;   dst = h_x1;   nq = 524288; break;
        case 2: src = wqv;  dst = h_wqv;  nq = 131072; break;
        case 3: src = wk;   dst = h_wk;   nq = 65536;  break;
        default: src = wout; dst = h_wout; nq = 65536; break;
    }
    const int i = blockIdx.x * 256 + threadIdx.x;
    if (i < nq) {
        float4 v = reinterpret_cast<const float4*>(src)[i];
        uint2 o = { pk(v.x, v.y), pk(v.z, v.w) };
        reinterpret_cast<uint2*>(dst)[i] = o;
    }
}

// ---------------------------------------------------------------------------
// fp16 GEMM: CTA tile (64*MT)x128, 256 thr (8 warps 4x2, warp (16*MT)x64).
// K chunks of 64 (8 iterations), 2-stage cp.async — halves per-chunk
// wait/sync overhead vs 32-wide chunks.
// A stage: (64*MT) rows x 64 k fp16, u32 pitch 36. B stage: 64 k x 128 n,
// u32 pitch 68.
// MODE 3 (MT=2): fused qv+k projection. MODE 2 (MT=1): g_o@h_wout + bias.
// ---------------------------------------------------------------------------
#define HA_LD 36
#define HB_LD 68

template <int MODE, int MT>
__global__ void __launch_bounds__(256, 2)
gemm_h(const float* __restrict__ bias, float* __restrict__ Cout)
{
    constexpr int STAGE = 64 * MT * HA_LD + 64 * HB_LD;
    extern __shared__ uint32_t sm[];
    const int tid  = threadIdx.x;
    const int lane = tid & 31;
    const int w    = tid >> 5;
    const int g    = lane >> 2;
    const int tg   = lane & 3;
    const int wr   = w >> 1;
    const int wc   = w & 1;
    const int row0 = blockIdx.y * (64 * MT);

    bool isQV = true;
    int col0, ncols;
    const __half* Ap;
    const __half* Wp;
    if (MODE == 3) {
        isQV = (blockIdx.x < 8);
        col0 = isQV ? blockIdx.x * 128 : (blockIdx.x - 8) * 128;
        ncols = isQV ? 1024 : 512;
        Ap = isQV ? h_x : h_x1;
        Wp = isQV ? h_wqv : h_wk;
    } else {
        col0 = blockIdx.x * 128;
        ncols = 512;
        Ap = g_o;
        Wp = h_wout;
    }

    uint32_t* const AsS[2] = { sm, sm + STAGE };
    uint32_t* const BsS[2] = { sm + 64 * MT * HA_LD, sm + STAGE + 64 * MT * HA_LD };

    float acc[MT][8][4] = {};

    // prologue: chunk 0  (A: (64*MT)x64 fp16 ; B: 64x128 fp16)
#pragma unroll
    for (int i = 0; i < 2 * MT; i++) {
        const int idx = tid + i * 256;
        const int r = idx >> 3, seg = idx & 7;
        CP16(smaddr(&AsS[0][r * HA_LD + seg * 4]),
             Ap + (size_t)(row0 + r) * 512 + seg * 8);
    }
#pragma unroll
    for (int i = 0; i < 4; i++) {
        const int idx = tid + i * 256;
        const int r = idx >> 4, q = idx & 15;
        CP16(smaddr(&BsS[0][r * HB_LD + q * 4]),
             Wp + (size_t)r * ncols + col0 + q * 8);
    }
    CPCOMMIT();

    for (int ch = 0; ch < 8; ch++) {
        CPWAIT0();
        __syncthreads();
        if (ch < 7) {
            const int k0 = (ch + 1) * 64;
            const int s  = (ch + 1) & 1;
#pragma unroll
            for (int i = 0; i < 2 * MT; i++) {
                const int idx = tid + i * 256;
                const int r = idx >> 3, seg = idx & 7;
                CP16(smaddr(&AsS[s][r * HA_LD + seg * 4]),
                     Ap + (size_t)(row0 + r) * 512 + k0 + seg * 8);
            }
#pragma unroll
            for (int i = 0; i < 4; i++) {
                const int idx = tid + i * 256;
                const int r = idx >> 4, q = idx & 15;
                CP16(smaddr(&BsS[s][r * HB_LD + q * 4]),
                     Wp + (size_t)(k0 + r) * ncols + col0 + q * 8);
            }
            CPCOMMIT();
        }
        const uint32_t* as = AsS[ch & 1];
        const __half* bsh = reinterpret_cast<const __half*>(BsS[ch & 1]);

#pragma unroll
        for (int kt = 0; kt < 4; kt++) {
            uint32_t a[MT][4];
#pragma unroll
            for (int mt = 0; mt < MT; mt++) {
                const int r = wr * 16 * MT + mt * 16;
                a[mt][0] = as[(r + g) * HA_LD + kt * 8 + tg];
                a[mt][1] = as[(r + g + 8) * HA_LD + kt * 8 + tg];
                a[mt][2] = as[(r + g) * HA_LD + kt * 8 + tg + 4];
                a[mt][3] = as[(r + g + 8) * HA_LD + kt * 8 + tg + 4];
            }
            uint32_t bfr[8][2];
#pragma unroll
            for (int ntp = 0; ntp < 4; ntp++) {
                const int kr   = kt * 16 + ((lane >> 3) & 1) * 8 + (lane & 7);
                const int ncol = wc * 64 + (ntp * 2 + (lane >> 4)) * 8;
                ldsm4t(bfr[ntp * 2][0], bfr[ntp * 2][1],
                       bfr[ntp * 2 + 1][0], bfr[ntp * 2 + 1][1],
                       smaddr(&bsh[kr * (HB_LD * 2) + ncol]));
            }
#pragma unroll
            for (int nt = 0; nt < 8; nt++)
#pragma unroll
                for (int mt = 0; mt < MT; mt++)
                    mma_h(acc[mt][nt], a[mt][0], a[mt][1], a[mt][2], a[mt][3],
                          bfr[nt][0], bfr[nt][1]);
        }
    }

#pragma unroll
    for (int mt = 0; mt < MT; mt++) {
#pragma unroll
        for (int nt = 0; nt < 8; nt++) {
#pragma unroll
            for (int half = 0; half < 2; half++) {
                const int row = row0 + wr * 16 * MT + mt * 16 + g + half * 8;
                const int col = col0 + wc * 64 + nt * 8 + 2 * tg;
                const float v0 = acc[mt][nt][half * 2 + 0];
                const float v1 = acc[mt][nt][half * 2 + 1];
                const int b = row >> 11, n = row & 2047;
                if (MODE == 3) {
                    __half* dst;
                    if (isQV) {
                        if (col < 512) {
                            const int h = col >> 6, d = col & 63;
                            dst = &g_q[((size_t)(b * 8 + h) * 2048 + n) * 64 + d];
                        } else {
                            const int c2 = col - 512;
                            const int h = c2 >> 6, d = c2 & 63;
                            dst = &g_v[((size_t)(b * 8 + h) * 2048 + n) * 64 + d];
                        }
                    } else {
                        const int h = col >> 6, d = col & 63;
                        dst = &g_k[((size_t)(b * 8 + h) * 2048 + n) * 64 + d];
                    }
                    *reinterpret_cast<uint32_t*>(dst) = pk(v0, v1);
                } else {
                    float* dst = &Cout[(size_t)row * 512 + col];
                    *reinterpret_cast<float2*>(dst) =
                        make_float2(v0 + bias[col], v1 + bias[col + 1]);
                }
            }
        }
    }
}

// ---------------------------------------------------------------------------
// Fused attention (round-14 proven config, UNCHANGED): 128 threads, 4 warps
// x 32 q-rows, hoisted Q fragments, 2-stage cp.async K/V/amat, P in regs.
// smem u32: Qs[128][36] | Ks[2][32][36] | Vs[2][32][36] | Am[2][128][36]
// ---------------------------------------------------------------------------
#define AQ_LD 36
#define ATT_SMEM_W (128 * AQ_LD + 4 * 32 * AQ_LD + 2 * 128 * AQ_LD)

__global__ void __launch_bounds__(128, 3)
attn_h(const float* __restrict__ amat,
       const float* __restrict__ dots_para,
       const float* __restrict__ mat_para)
{
    extern __shared__ uint32_t sm[];
    uint32_t* const Qs = sm;
    uint32_t* const KsS[2] = { sm + 128 * AQ_LD, sm + 160 * AQ_LD };
    uint32_t* const VsS[2] = { sm + 192 * AQ_LD, sm + 224 * AQ_LD };
    uint32_t* const AmS[2] = { sm + 256 * AQ_LD, sm + 384 * AQ_LD };

    const int tid  = threadIdx.x;
    const int lane = tid & 31;
    const int w    = tid >> 5;
    const int g    = lane >> 2;
    const int tg   = lane & 3;
    const int b  = blockIdx.z, h = blockIdx.y;
    const int n0 = blockIdx.x * 128;

    const float qscale = 0.125f * dots_para[0] * 1.44269504f;
    const float mp = mat_para[0] * 1.44269504f;

    const size_t qbase  = ((size_t)(b * 8 + h) * 2048 + n0) * 64;
    const size_t kvbase = (size_t)(b * 8 + h) * 2048 * 64;
    const size_t abase  = ((size_t)(b * 8 + h) * 2048 + n0) * 2048;

#pragma unroll
    for (int i = 0; i < 8; i++) {
        const int idx = tid + i * 128;
        const int r = idx >> 3, q = idx & 7;
        CP16(smaddr(&Qs[r * AQ_LD + q * 4]), g_q + qbase + (size_t)r * 64 + q * 8);
    }
#pragma unroll
    for (int i = 0; i < 2; i++) {
        const int idx = tid + i * 128;
        const int r = idx >> 3, q = idx & 7;
        CP16(smaddr(&KsS[0][r * AQ_LD + q * 4]), g_k + kvbase + (size_t)r * 64 + q * 8);
        CP16(smaddr(&VsS[0][r * AQ_LD + q * 4]), g_v + kvbase + (size_t)r * 64 + q * 8);
    }
#pragma unroll
    for (int i = 0; i < 8; i++) {
        const int idx = tid + i * 128;
        const int r = idx >> 3, c = (idx & 7) * 4;
        CP16(smaddr(&AmS[0][r * AQ_LD + c]), amat + abase + (size_t)r * 2048 + c);
    }
    CPCOMMIT();

    uint32_t qf[4][2][4];
    float O[2][8][4] = {};
    float rl[2][2] = {};

    for (int ch = 0; ch < 64; ch++) {
        CPWAIT0();
        __syncthreads();
        if (ch == 0) {
            const __half* Qsh = reinterpret_cast<const __half*>(Qs);
#pragma unroll
            for (int kt = 0; kt < 4; kt++) {
#pragma unroll
                for (int mt = 0; mt < 2; mt++) {
                    const int mr = w * 32 + mt * 16 + (lane & 15);
                    const int kc = kt * 16 + (lane >> 4) * 8;
                    ldsm4(qf[kt][mt][0], qf[kt][mt][1], qf[kt][mt][2], qf[kt][mt][3],
                          smaddr(&Qsh[mr * (AQ_LD * 2) + kc]));
                }
            }
        }
        if (ch < 63) {
            const size_t m1 = (size_t)(ch + 1) * 32;
            const int s = (ch + 1) & 1;
#pragma unroll
            for (int i = 0; i < 2; i++) {
                const int idx = tid + i * 128;
                const int r = idx >> 3, q = idx & 7;
                CP16(smaddr(&KsS[s][r * AQ_LD + q * 4]),
                     g_k + kvbase + (m1 + r) * 64 + q * 8);
                CP16(smaddr(&VsS[s][r * AQ_LD + q * 4]),
                     g_v + kvbase + (m1 + r) * 64 + q * 8);
            }
#pragma unroll
            for (int i = 0; i < 8; i++) {
                const int idx = tid + i * 128;
                const int r = idx >> 3, c = (idx & 7) * 4;
                CP16(smaddr(&AmS[s][r * AQ_LD + c]),
                     amat + abase + (size_t)r * 2048 + m1 + c);
            }
            CPCOMMIT();
        }
        const __half* Ksh = reinterpret_cast<const __half*>(KsS[ch & 1]);
        const __half* Vsh = reinterpret_cast<const __half*>(VsS[ch & 1]);
        const float*  Am  = reinterpret_cast<const float*>(AmS[ch & 1]);

        float S[2][4][4] = {};
#pragma unroll
        for (int kt = 0; kt < 4; kt++) {
#pragma unroll
            for (int ntp = 0; ntp < 2; ntp++) {
                uint32_t kb0, kb1, kb2, kb3;
                const int nr = ntp * 16 + ((lane >> 4) & 1) * 8 + (lane & 7);
                const int kc = kt * 16 + ((lane >> 3) & 1) * 8;
                ldsm4(kb0, kb1, kb2, kb3, smaddr(&Ksh[nr * (AQ_LD * 2) + kc]));
#pragma unroll
                for (int mt = 0; mt < 2; mt++) {
                    mma_h(S[mt][ntp * 2],     qf[kt][mt][0], qf[kt][mt][1],
                          qf[kt][mt][2], qf[kt][mt][3], kb0, kb1);
                    mma_h(S[mt][ntp * 2 + 1], qf[kt][mt][0], qf[kt][mt][1],
                          qf[kt][mt][2], qf[kt][mt][3], kb2, kb3);
                }
            }
        }

#pragma unroll
        for (int j = 0; j < 2; j++) {
            uint32_t pva[2][4];
#pragma unroll
            for (int mt = 0; mt < 2; mt++) {
#pragma unroll
                for (int t = 0; t < 2; t++) {
                    const int nt = j * 2 + t;
                    const int rowA = w * 32 + mt * 16 + g;
                    const int acol = nt * 8 + 2 * tg;
                    const float2 amA = *reinterpret_cast<const float2*>(
                        &Am[rowA * AQ_LD + acol]);
                    const float2 amB = *reinterpret_cast<const float2*>(
                        &Am[(rowA + 8) * AQ_LD + acol]);
                    const float p0 = ex2f(S[mt][nt][0] * qscale + amA.x * mp);
                    const float p1 = ex2f(S[mt][nt][1] * qscale + amA.y * mp);
                    const float p2 = ex2f(S[mt][nt][2] * qscale + amB.x * mp);
                    const float p3 = ex2f(S[mt][nt][3] * qscale + amB.y * mp);
                    rl[mt][0] += p0 + p1;
                    rl[mt][1] += p2 + p3;
                    pva[mt][t * 2 + 0] = pk(p0, p1);
                    pva[mt][t * 2 + 1] = pk(p2, p3);
                }
            }
            uint32_t vb[8][2];
#pragma unroll
            for (int ntp = 0; ntp < 4; ntp++) {
                const int mr = j * 16 + ((lane >> 3) & 1) * 8 + (lane & 7);
                const int dc = (ntp * 2 + (lane >> 4)) * 8;
                ldsm4t(vb[ntp * 2][0], vb[ntp * 2][1],
                       vb[ntp * 2 + 1][0], vb[ntp * 2 + 1][1],
                       smaddr(&Vsh[mr * (AQ_LD * 2) + dc]));
            }
#pragma unroll
            for (int nt = 0; nt < 8; nt++)
#pragma unroll
                for (int mt = 0; mt < 2; mt++)
                    mma_h(O[mt][nt], pva[mt][0], pva[mt][1], pva[mt][2], pva[mt][3],
                          vb[nt][0], vb[nt][1]);
        }
    }

#pragma unroll
    for (int mt = 0; mt < 2; mt++) {
        float r0 = rl[mt][0], r1 = rl[mt][1];
#pragma unroll
        for (int off = 1; off <= 2; off <<= 1) {
            r0 += __shfl_xor_sync(0xffffffffu, r0, off);
            r1 += __shfl_xor_sync(0xffffffffu, r1, off);
        }
        const float inv0 = 1.0f / r0;
        const float inv1 = 1.0f / r1;
        const int grow = n0 + w * 32 + mt * 16 + g;
#pragma unroll
        for (int nt = 0; nt < 8; nt++) {
            const int col = h * 64 + nt * 8 + 2 * tg;
            *reinterpret_cast<uint32_t*>(&g_o[((size_t)b * 2048 + grow) * 512 + col]) =
                pk(O[mt][nt][0] * inv0, O[mt][nt][1] * inv0);
            *reinterpret_cast<uint32_t*>(&g_o[((size_t)b * 2048 + grow + 8) * 512 + col]) =
                pk(O[mt][nt][2] * inv1, O[mt][nt][3] * inv1);
        }
    }
}

// ---------------------------------------------------------------------------
extern "C" void kernel_launch(void* const* d_in, const int* in_sizes, int n_in,
                              void* d_out, int out_size)
{
    const float* x    = (const float*)d_in[0];
    const float* x1   = (const float*)d_in[1];
    const float* amat = (const float*)d_in[2];
    const float* dp   = (const float*)d_in[3];
    const float* mp   = (const float*)d_in[4];
    const float* Wqv  = (const float*)d_in[5];
    const float* Wk   = (const float*)d_in[6];
    const float* Wout = (const float*)d_in[7];
    const float* bout = (const float*)d_in[8];
    float* out = (float*)d_out;

    const int gsmem2 = 2 * (128 * HA_LD + 64 * HB_LD) * (int)sizeof(uint32_t); // 71,680
    const int gsmem1 = 2 * (64 * HA_LD + 64 * HB_LD) * (int)sizeof(uint32_t);  // 53,248
    const int asmem  = ATT_SMEM_W * (int)sizeof(uint32_t);                     // 73,728
    cudaFuncSetAttribute((const void*)attn_h,
                         cudaFuncAttributeMaxDynamicSharedMemorySize, asmem);
    cudaFuncSetAttribute((const void*)gemm_h<3, 2>,
                         cudaFuncAttributeMaxDynamicSharedMemorySize, gsmem2);
    cudaFuncSetAttribute((const void*)gemm_h<2, 1>,
                         cudaFuncAttributeMaxDynamicSharedMemorySize, gsmem1);

    // fp32 -> fp16 staging
    convert_k<<<dim3(2048, 5), 256>>>(x, x1, Wqv, Wk, Wout);
    // fused q,v,k projection: 128x128 tiles, K-chunk 64 -> 384 CTAs
    gemm_h<3, 2><<<dim3(12, 32), 256, gsmem2>>>(nullptr, nullptr);
    // fused attention: 4 fat warps, hoisted Q frags (unchanged)
    attn_h<<<dim3(16, 8, 2), 128, asmem>>>(amat, dp, mp);
    // output projection + bias: 64x128 tiles, K-chunk 64 -> 256 CTAs
    gemm_h<2, 1><<<dim3(4, 64), 256, gsmem1>>>(bout, out);
}